// round 6
// baseline (speedup 1.0000x reference)
#include <cuda_runtime.h>
#include <cuda_bf16.h>
#include <cstdint>

#define BB 128
#define TT 100
#define NN 2048
#define OO 512
#define DLY 10

#define ALPHA_F   0.90483741803595957316f   // exp(-1/10)
#define DEC_F     0.95122942450071400910f   // exp(-1/20)
#define CDEC_F    0.04877057549928599090f   // 1 - exp(-1/20)
#define THRESH_F  0.02f
#define A_PLUS_F  1e-4f
#define A_MINUS_F 1e-4f
#define INVB_F    0.0078125f                // 1/128, exact

#define SPLIT_A 16          // hw K-chunks of 128 (K=2048)
#define SPLIT_I 4           // iew K-chunks of 128 (K=512)

typedef __nv_bfloat16 bf16;

// ---------------- state (static device globals; no allocation) ----------------
__device__ bf16  g_l1b [(size_t)TT*BB*NN];    // l1 spikes, bf16 (exact 0/1)
__device__ bf16  g_tr1h[(size_t)TT*BB*NN];    // tr1 hi split per step
__device__ bf16  g_tr1l[(size_t)TT*BB*NN];    // tr1 lo split per step
__device__ float g_v2 [BB*OO];
__device__ float g_vi [BB*OO];
__device__ float g_tr2[BB*OO];
__device__ float g_tri[BB*OO];
__device__ bf16  g_tr2h[BB*OO], g_tr2l[BB*OO];
__device__ bf16  g_trih[BB*OO], g_tril[BB*OO];
__device__ bf16  g_bufb[BB*DLY*OO];           // inh spike delay buffer (exact 0/1)
__device__ float g_hw [(size_t)OO*NN];
__device__ bf16  g_hwh[(size_t)OO*NN], g_hwm[(size_t)OO*NN], g_hwl[(size_t)OO*NN];
__device__ float g_iew[OO*OO];
__device__ bf16  g_iewh[OO*OO], g_iewm[OO*OO], g_iewl[OO*OO];
__device__ float g_ediag[OO];
__device__ float g_mtr2[OO];
__device__ float g_pA[SPLIT_A*BB*OO];
__device__ float g_pI[SPLIT_I*BB*OO];
__device__ int   g_nzcnt[NN];
__device__ int   g_nzcol[(size_t)NN*NN];
__device__ float g_nzval[(size_t)NN*NN];

__device__ __forceinline__ void split3(float w, bf16& h, bf16& m, bf16& l) {
    h = __float2bfloat16(w);
    float r1 = __fadd_rn(w, -__bfloat162float(h));
    m = __float2bfloat16(r1);
    float r2 = __fadd_rn(r1, -__bfloat162float(m));
    l = __float2bfloat16(r2);
}
__device__ __forceinline__ void split2(float w, bf16& h, bf16& l) {
    h = __float2bfloat16(w);
    l = __float2bfloat16(__fadd_rn(w, -__bfloat162float(h)));
}

// ---------------- init: reset state each launch (graph replays!) ----------------
__global__ void k_init(const float* __restrict__ hw_in,
                       const float* __restrict__ eiw_in,
                       const float* __restrict__ iew_in) {
    int i = blockIdx.x * blockDim.x + threadIdx.x;   // grid covers OO*NN = 1M
    if (i < OO*NN) {
        float w = hw_in[i];
        g_hw[i] = w;
        split3(w, g_hwh[i], g_hwm[i], g_hwl[i]);
    }
    if (i < BB*DLY*OO) g_bufb[i] = __float2bfloat16(0.f);
    if (i < BB*OO) {
        g_v2[i]=0.f; g_vi[i]=0.f; g_tr2[i]=0.f; g_tri[i]=0.f;
        bf16 z = __float2bfloat16(0.f);
        g_tr2h[i]=z; g_tr2l[i]=z; g_trih[i]=z; g_tril[i]=z;
    }
    if (i < OO*OO) {
        int r = i / OO, c = i - r*OO;
        float w = (r == c) ? 0.f : iew_in[i];
        g_iew[i] = w;
        split3(w, g_iewh[i], g_iewm[i], g_iewl[i]);
    }
    if (i < OO) g_ediag[i] = eiw_in[i*OO + i];
}

// ---------------- CSR build of input_weight (warp per row) ----------------
__global__ void k_csr(const float* __restrict__ W) {
    int wid  = (blockIdx.x * blockDim.x + threadIdx.x) >> 5;
    int lane = threadIdx.x & 31;
    if (wid >= NN) return;
    int cnt = 0;
    for (int base = 0; base < NN; base += 32) {
        float w = W[wid*NN + base + lane];
        unsigned m = __ballot_sync(0xffffffffu, w != 0.f);
        if (w != 0.f) {
            int pos = cnt + __popc(m & ((1u << lane) - 1u));
            g_nzcol[(size_t)wid*NN + pos] = base + lane;
            g_nzval[(size_t)wid*NN + pos] = w;
        }
        cnt += __popc(m);
    }
    if (lane == 0) g_nzcnt[wid] = cnt;
}

// ---------------- layer 1: all T steps in one launch ----------------
__global__ __launch_bounds__(256) void k_layer1_all(const float* __restrict__ x,
                                                    float* __restrict__ out_l1) {
    int idx = blockIdx.x * 256 + threadIdx.x;      // grid == BB*NN
    int b = idx >> 11;
    int n = idx & (NN - 1);
    int cnt = g_nzcnt[n];
    const int*   cp = g_nzcol + (size_t)n*NN;
    const float* vp = g_nzval + (size_t)n*NN;
    const float* xb = x + (size_t)b*TT*NN;
    float v = 0.f, tr = 0.f;
    for (int t = 0; t < TT; t++) {
        const float* xr = xb + (size_t)t*NN;
        float acc = 0.f;
        for (int j = 0; j < cnt; j++) acc = fmaf(xr[cp[j]], vp[j], acc);
        v = fmaf(ALPHA_F, v, acc);
        float s = (v > THRESH_F) ? 1.f : 0.f;
        v = (v > THRESH_F) ? 0.f : v;
        tr = fmaf(DEC_F, tr, __fmul_rn(CDEC_F, s));
        size_t o = ((size_t)b*TT + t)*NN + n;
        out_l1[o] = s;
        size_t ot = ((size_t)t*BB + b)*NN + n;
        g_l1b[ot] = __float2bfloat16(s);
        bf16 h, l; split2(tr, h, l);
        g_tr1h[ot] = h; g_tr1l[ot] = l;
    }
}

// ---------------- MMA gemm: partials for l1v (hw, 3-split) and io (iew, 3-split) ----------------
// grid: x = 8 q-tiles (64 q), y = 20 chunks (16 hw + 4 iew). 256 threads.
// Dynamic smem: sA[128][136] bf16 + sB[64][136] bf16 = 52224 bytes.
extern __shared__ __align__(16) char smem_raw[];
__global__ __launch_bounds__(256) void k_gemm_mma(int t, int tm) {
    bf16* sA = (bf16*)smem_raw;        // [128][136]
    bf16* sB = sA + 128*136;           // [64][136]
    int chunk = blockIdx.y, qt = blockIdx.x;
    const bf16 *Asrc, *W0, *W1, *W2;
    size_t astride; int wstride, k0; float* part;
    if (chunk < SPLIT_A) {
        Asrc = g_l1b + (size_t)t*BB*NN; astride = NN; k0 = chunk*128;
        W0 = g_hwh; W1 = g_hwm; W2 = g_hwl; wstride = NN;
        part = g_pA + (size_t)chunk*BB*OO;
    } else {
        Asrc = g_bufb + tm*OO; astride = (size_t)DLY*OO; k0 = (chunk - SPLIT_A)*128;
        W0 = g_iewh; W1 = g_iewm; W2 = g_iewl; wstride = OO;
        part = g_pI + (size_t)(chunk - SPLIT_A)*BB*OO;
    }
    int q0 = qt*64;
    int tid = threadIdx.x;

    // load A tile: 128 rows x 128 bf16
    #pragma unroll
    for (int i = 0; i < 8; i++) {
        int idx = tid + i*256;
        int r = idx >> 4, c8 = idx & 15;
        *(uint4*)(sA + r*136 + c8*8) = *(const uint4*)(Asrc + (size_t)r*astride + k0 + c8*8);
    }

    int w = tid >> 5, lane = tid & 31, g = lane >> 2, qi = lane & 3;
    float acc[8][4];
    #pragma unroll
    for (int j = 0; j < 8; j++) { acc[j][0]=0.f; acc[j][1]=0.f; acc[j][2]=0.f; acc[j][3]=0.f; }

    const bf16* Ws[3] = {W0, W1, W2};
    for (int s = 0; s < 3; s++) {
        __syncthreads();
        #pragma unroll
        for (int i = 0; i < 4; i++) {
            int idx = tid + i*256;
            int r = idx >> 4, c8 = idx & 15;
            *(uint4*)(sB + r*136 + c8*8) = *(const uint4*)(Ws[s] + (size_t)(q0 + r)*wstride + k0 + c8*8);
        }
        __syncthreads();
        #pragma unroll
        for (int k16 = 0; k16 < 8; k16++) {
            int kb = k16*16 + qi*2;
            uint32_t a0 = *(const uint32_t*)(sA + (16*w + g    )*136 + kb    );
            uint32_t a1 = *(const uint32_t*)(sA + (16*w + g + 8)*136 + kb    );
            uint32_t a2 = *(const uint32_t*)(sA + (16*w + g    )*136 + kb + 8);
            uint32_t a3 = *(const uint32_t*)(sA + (16*w + g + 8)*136 + kb + 8);
            #pragma unroll
            for (int j = 0; j < 8; j++) {
                uint32_t b0 = *(const uint32_t*)(sB + (j*8 + g)*136 + kb    );
                uint32_t b1 = *(const uint32_t*)(sB + (j*8 + g)*136 + kb + 8);
                asm volatile(
                    "mma.sync.aligned.m16n8k16.row.col.f32.bf16.bf16.f32 "
                    "{%0,%1,%2,%3},{%4,%5,%6,%7},{%8,%9},{%0,%1,%2,%3};\n"
                    : "+f"(acc[j][0]), "+f"(acc[j][1]), "+f"(acc[j][2]), "+f"(acc[j][3])
                    : "r"(a0), "r"(a1), "r"(a2), "r"(a3), "r"(b0), "r"(b1));
            }
        }
    }
    int m0 = 16*w + g;
    #pragma unroll
    for (int j = 0; j < 8; j++) {
        int qc = q0 + j*8 + qi*2;
        *(float2*)(part + (size_t)m0*OO + qc)       = make_float2(acc[j][0], acc[j][1]);
        *(float2*)(part + (size_t)(m0 + 8)*OO + qc) = make_float2(acc[j][2], acc[j][3]);
    }
}

// ---------------- epilogue: chunk-sum + l2/inh LIF + traces + splits + buf + reductions ----------------
__global__ __launch_bounds__(256) void k_epi(float* __restrict__ out_l2, int t, int tm) {
    int qb = blockIdx.x * 16;
    int tq = threadIdx.x & 15;
    int tb = threadIdx.x >> 4;       // 0..15
    int q  = qb + tq;
    __shared__ float sh[3][16][16];

    float r2 = 0.f, ri = 0.f, rd = 0.f;
    for (int j = 0; j < 8; j++) {
        int b  = tb + 16*j;
        int bo = b*OO + q;
        float l1v = 0.f, io = 0.f;
        #pragma unroll
        for (int s = 0; s < SPLIT_A; s++) l1v = __fadd_rn(l1v, g_pA[(size_t)s*BB*OO + bo]);
        #pragma unroll
        for (int s = 0; s < SPLIT_I; s++) io  = __fadd_rn(io,  g_pI[(size_t)s*BB*OO + bo]);
        float v = fmaf(ALPHA_F, g_v2[bo], __fadd_rn(l1v, -io));
        float s2 = (v > THRESH_F) ? 1.f : 0.f;
        g_v2[bo] = (v > THRESH_F) ? 0.f : v;
        out_l2[((size_t)b*TT + t)*OO + q] = s2;
        float t2 = fmaf(DEC_F, g_tr2[bo], __fmul_rn(CDEC_F, s2));
        g_tr2[bo] = t2;
        { bf16 h, l; split2(t2, h, l); g_tr2h[bo] = h; g_tr2l[bo] = l; }
        float inh_in = __fmul_rn(s2, g_ediag[q]);
        float vv = fmaf(ALPHA_F, g_vi[bo], inh_in);
        float si = (vv > THRESH_F) ? 1.f : 0.f;
        g_vi[bo] = (vv > THRESH_F) ? 0.f : vv;
        g_bufb[((size_t)b*DLY + tm)*OO + q] = __float2bfloat16(si);
        float ti = fmaf(DEC_F, g_tri[bo], __fmul_rn(CDEC_F, si));
        g_tri[bo] = ti;
        { bf16 h, l; split2(ti, h, l); g_trih[bo] = h; g_tril[bo] = l; }
        r2 += t2; ri += ti; rd = fmaf(ti, t2, rd);
    }
    sh[0][tb][tq] = r2; sh[1][tb][tq] = ri; sh[2][tb][tq] = rd;
    __syncthreads();
    if (tb == 0) {
        float s2 = 0.f, si = 0.f, sd = 0.f;
        for (int g = 0; g < 16; g++) { s2 += sh[0][g][tq]; si += sh[1][g][tq]; sd += sh[2][g][tq]; }
        float m2 = s2 * INVB_F, mi = si * INVB_F;
        g_mtr2[q] = m2;
        float e = g_ediag[q];
        float dw = fmaf(A_PLUS_F, __fmul_rn(sd, INVB_F),
                        -__fmul_rn(__fmul_rn(A_MINUS_F, e), mi));
        g_ediag[q] = __fadd_rn(e, dw);
    }
}

// ---------------- MMA plasticity: hebb[q,p] = sum_b post[b,q]*pre[b,p] via 2x2 bf16 splits ----------------
// grid: x = 40 p-tiles (0..31 hw, 32..39 iew), y = 8 q-tiles of 64. 256 threads.
// Dynamic smem: sAh[64][136] + sAl[64][136] + sB[64][136] = 52224 bytes.
__global__ __launch_bounds__(256) void k_plast_mma(int t) {
    bf16* sAh = (bf16*)smem_raw;        // [64 q][136 (k=b)]
    bf16* sAl = sAh + 64*136;
    bf16* sB  = sAl + 64*136;           // [64 p][136 (k=b)]
    int bx = blockIdx.x;
    int mode = (bx >= 32);
    int p0 = (mode ? (bx - 32) : bx) * 64;
    int q0 = blockIdx.y * 64;
    const bf16* preh = mode ? g_trih : (g_tr1h + (size_t)t*BB*NN);
    const bf16* prel = mode ? g_tril : (g_tr1l + (size_t)t*BB*NN);
    int P = mode ? OO : NN;
    float* W = mode ? g_iew : g_hw;
    bf16 *Wh = mode ? g_iewh : g_hwh, *Wm = mode ? g_iewm : g_hwm, *Wl = mode ? g_iewl : g_hwl;

    int tid = threadIdx.x;
    // load+transpose post (tr2) hi/lo tiles: [128 b][64 q] -> sA[q][b]
    for (int i = 0; i < 32; i++) {
        int idx = tid + i*256;           // 8192
        int b = idx >> 6, q = idx & 63;
        sAh[q*136 + b] = g_tr2h[b*OO + q0 + q];
        sAl[q*136 + b] = g_tr2l[b*OO + q0 + q];
    }

    int w = tid >> 5, lane = tid & 31, g = lane >> 2, qi = lane & 3;
    float acc[4][4];
    #pragma unroll
    for (int mi = 0; mi < 4; mi++) { acc[mi][0]=0.f; acc[mi][1]=0.f; acc[mi][2]=0.f; acc[mi][3]=0.f; }

    const bf16* Bs[2] = {preh, prel};
    for (int s = 0; s < 2; s++) {
        __syncthreads();
        for (int i = 0; i < 32; i++) {
            int idx = tid + i*256;
            int b = idx >> 6, p = idx & 63;
            sB[p*136 + b] = Bs[s][(size_t)b*P + p0 + p];
        }
        __syncthreads();
        #pragma unroll
        for (int k16 = 0; k16 < 8; k16++) {
            int kb = k16*16 + qi*2;
            uint32_t b0 = *(const uint32_t*)(sB + (w*8 + g)*136 + kb    );
            uint32_t b1 = *(const uint32_t*)(sB + (w*8 + g)*136 + kb + 8);
            #pragma unroll
            for (int mi = 0; mi < 4; mi++) {
                #pragma unroll
                for (int as = 0; as < 2; as++) {
                    const bf16* A = as ? sAl : sAh;
                    uint32_t a0 = *(const uint32_t*)(A + (mi*16 + g    )*136 + kb    );
                    uint32_t a1 = *(const uint32_t*)(A + (mi*16 + g + 8)*136 + kb    );
                    uint32_t a2 = *(const uint32_t*)(A + (mi*16 + g    )*136 + kb + 8);
                    uint32_t a3 = *(const uint32_t*)(A + (mi*16 + g + 8)*136 + kb + 8);
                    asm volatile(
                        "mma.sync.aligned.m16n8k16.row.col.f32.bf16.bf16.f32 "
                        "{%0,%1,%2,%3},{%4,%5,%6,%7},{%8,%9},{%0,%1,%2,%3};\n"
                        : "+f"(acc[mi][0]), "+f"(acc[mi][1]), "+f"(acc[mi][2]), "+f"(acc[mi][3])
                        : "r"(a0), "r"(a1), "r"(a2), "r"(a3), "r"(b0), "r"(b1));
                }
            }
        }
    }

    int pc = p0 + w*8 + qi*2;
    #pragma unroll
    for (int mi = 0; mi < 4; mi++) {
        #pragma unroll
        for (int half = 0; half < 2; half++) {
            int qq = q0 + mi*16 + g + half*8;
            float h0 = acc[mi][half*2 + 0], h1 = acc[mi][half*2 + 1];
            float mean = g_mtr2[qq];
            size_t base = (size_t)qq*P + pc;
            float2 wv = *(float2*)(W + base);
            float dw0 = fmaf(A_PLUS_F, __fmul_rn(h0, INVB_F),
                             -__fmul_rn(__fmul_rn(A_MINUS_F, wv.x), mean));
            float dw1 = fmaf(A_PLUS_F, __fmul_rn(h1, INVB_F),
                             -__fmul_rn(__fmul_rn(A_MINUS_F, wv.y), mean));
            float nw0 = __fadd_rn(wv.x, dw0);
            float nw1 = __fadd_rn(wv.y, dw1);
            if (mode && qq == pc)     nw0 = 0.f;
            if (mode && qq == pc + 1) nw1 = 0.f;
            *(float2*)(W + base) = make_float2(nw0, nw1);
            bf16 h, m, l, h2, m2, l2;
            split3(nw0, h, m, l);
            split3(nw1, h2, m2, l2);
            *(__nv_bfloat162*)(Wh + base) = __nv_bfloat162(h, h2);
            *(__nv_bfloat162*)(Wm + base) = __nv_bfloat162(m, m2);
            *(__nv_bfloat162*)(Wl + base) = __nv_bfloat162(l, l2);
        }
    }
}

// ---------------- launch ----------------
extern "C" void kernel_launch(void* const* d_in, const int* in_sizes, int n_in,
                              void* d_out, int out_size) {
    const float* x      = (const float*)d_in[0];
    const float* win    = (const float*)d_in[1];
    const float* hw_in  = (const float*)d_in[2];
    const float* eiw_in = (const float*)d_in[3];
    const float* iew_in = (const float*)d_in[4];
    float* out_l1 = (float*)d_out;
    float* out_l2 = out_l1 + (size_t)BB*TT*NN;

    const int smbytes = (128*136 + 64*136) * 2;   // 52224
    cudaFuncSetAttribute(k_gemm_mma,  cudaFuncAttributeMaxDynamicSharedMemorySize, smbytes);
    cudaFuncSetAttribute(k_plast_mma, cudaFuncAttributeMaxDynamicSharedMemorySize, smbytes);

    k_init<<<(OO*NN)/256, 256>>>(hw_in, eiw_in, iew_in);
    k_csr<<<256, 256>>>(win);
    k_layer1_all<<<(BB*NN)/256, 256>>>(x, out_l1);

    for (int t = 0; t < TT; t++) {
        int tm = t % DLY;
        k_gemm_mma<<<dim3(8, SPLIT_A + SPLIT_I), 256, smbytes>>>(t, tm);
        k_epi<<<32, 256>>>(out_l2, t, tm);
        k_plast_mma<<<dim3(40, 8), 256, smbytes>>>(t);
    }
}

// round 7
// speedup vs baseline: 1.2348x; 1.2348x over previous
#include <cuda_runtime.h>
#include <cuda_bf16.h>
#include <cstdint>

#define BB 128
#define TT 100
#define NN 2048
#define OO 512
#define DLY 10

#define ALPHA_F   0.90483741803595957316f   // exp(-1/10)
#define DEC_F     0.95122942450071400910f   // exp(-1/20)
#define CDEC_F    0.04877057549928599090f   // 1 - exp(-1/20)
#define THRESH_F  0.02f
#define A_PLUS_F  1e-4f
#define A_MINUS_F 1e-4f
#define INVB_F    0.0078125f                // 1/128, exact

#define SPLIT_A 16          // hw K-chunks of 128 (K=2048)
#define SPLIT_I 4           // iew K-chunks of 128 (K=512)

typedef __nv_bfloat16 bf16;

// ---------------- state (static device globals; no allocation) ----------------
__device__ bf16  g_l1b [(size_t)TT*BB*NN];    // l1 spikes, bf16 (exact 0/1)
__device__ bf16  g_tr1h[(size_t)TT*BB*NN];    // tr1 hi split per step
__device__ bf16  g_tr1l[(size_t)TT*BB*NN];    // tr1 lo split per step
__device__ float g_v2 [BB*OO];
__device__ float g_vi [BB*OO];
__device__ float g_tr2[BB*OO];
__device__ float g_tri[BB*OO];
__device__ bf16  g_tr2h[BB*OO], g_tr2l[BB*OO];
__device__ bf16  g_trih[BB*OO], g_tril[BB*OO];
__device__ bf16  g_bufb[BB*DLY*OO];           // inh spike delay buffer (exact 0/1)
__device__ float g_hw [(size_t)OO*NN];
__device__ bf16  g_hwh[(size_t)OO*NN], g_hwm[(size_t)OO*NN], g_hwl[(size_t)OO*NN];
__device__ float g_iew[OO*OO];
__device__ bf16  g_iewh[OO*OO], g_iewm[OO*OO], g_iewl[OO*OO];
__device__ float g_ediag[OO];
__device__ float g_mtr2[OO];
__device__ float g_pA[SPLIT_A*BB*OO];
__device__ float g_pI[SPLIT_I*BB*OO];
__device__ int   g_nzcnt[NN];
__device__ int   g_nzcol[(size_t)NN*NN];
__device__ float g_nzval[(size_t)NN*NN];

__device__ __forceinline__ void split3(float w, bf16& h, bf16& m, bf16& l) {
    h = __float2bfloat16(w);
    float r1 = __fadd_rn(w, -__bfloat162float(h));
    m = __float2bfloat16(r1);
    float r2 = __fadd_rn(r1, -__bfloat162float(m));
    l = __float2bfloat16(r2);
}
__device__ __forceinline__ void split2(float w, bf16& h, bf16& l) {
    h = __float2bfloat16(w);
    l = __float2bfloat16(__fadd_rn(w, -__bfloat162float(h)));
}

// ---------------- init ----------------
__global__ void k_init(const float* __restrict__ hw_in,
                       const float* __restrict__ eiw_in,
                       const float* __restrict__ iew_in) {
    int i = blockIdx.x * blockDim.x + threadIdx.x;   // grid covers OO*NN = 1M
    if (i < OO*NN) {
        float w = hw_in[i];
        g_hw[i] = w;
        split3(w, g_hwh[i], g_hwm[i], g_hwl[i]);
    }
    if (i < BB*DLY*OO) g_bufb[i] = __float2bfloat16(0.f);
    if (i < BB*OO) {
        g_v2[i]=0.f; g_vi[i]=0.f; g_tr2[i]=0.f; g_tri[i]=0.f;
        bf16 z = __float2bfloat16(0.f);
        g_tr2h[i]=z; g_tr2l[i]=z; g_trih[i]=z; g_tril[i]=z;
    }
    if (i < OO*OO) {
        int r = i / OO, c = i - r*OO;
        float w = (r == c) ? 0.f : iew_in[i];
        g_iew[i] = w;
        split3(w, g_iewh[i], g_iewm[i], g_iewl[i]);
    }
    if (i < OO) g_ediag[i] = eiw_in[i*OO + i];
}

// ---------------- CSR build of input_weight ----------------
__global__ void k_csr(const float* __restrict__ W) {
    int wid  = (blockIdx.x * blockDim.x + threadIdx.x) >> 5;
    int lane = threadIdx.x & 31;
    if (wid >= NN) return;
    int cnt = 0;
    for (int base = 0; base < NN; base += 32) {
        float w = W[wid*NN + base + lane];
        unsigned m = __ballot_sync(0xffffffffu, w != 0.f);
        if (w != 0.f) {
            int pos = cnt + __popc(m & ((1u << lane) - 1u));
            g_nzcol[(size_t)wid*NN + pos] = base + lane;
            g_nzval[(size_t)wid*NN + pos] = w;
        }
        cnt += __popc(m);
    }
    if (lane == 0) g_nzcnt[wid] = cnt;
}

// ---------------- layer 1: all T steps in one launch ----------------
__global__ __launch_bounds__(256) void k_layer1_all(const float* __restrict__ x,
                                                    float* __restrict__ out_l1) {
    int idx = blockIdx.x * 256 + threadIdx.x;      // grid == BB*NN
    int b = idx >> 11;
    int n = idx & (NN - 1);
    int cnt = g_nzcnt[n];
    const int*   cp = g_nzcol + (size_t)n*NN;
    const float* vp = g_nzval + (size_t)n*NN;
    const float* xb = x + (size_t)b*TT*NN;
    float v = 0.f, tr = 0.f;
    for (int t = 0; t < TT; t++) {
        const float* xr = xb + (size_t)t*NN;
        float acc = 0.f;
        for (int j = 0; j < cnt; j++) acc = fmaf(xr[cp[j]], vp[j], acc);
        v = fmaf(ALPHA_F, v, acc);
        float s = (v > THRESH_F) ? 1.f : 0.f;
        v = (v > THRESH_F) ? 0.f : v;
        tr = fmaf(DEC_F, tr, __fmul_rn(CDEC_F, s));
        size_t o = ((size_t)b*TT + t)*NN + n;
        out_l1[o] = s;
        size_t ot = ((size_t)t*BB + b)*NN + n;
        g_l1b[ot] = __float2bfloat16(s);
        bf16 h, l; split2(tr, h, l);
        g_tr1h[ot] = h; g_tr1l[ot] = l;
    }
}

extern __shared__ __align__(16) char smem_raw[];

// ---------------- MMA gemm: partials for l1v (hw, 3-split) and io (iew, 3-split) ----------------
// grid: x = 8 q-tiles (64 q), y = 2 m-tiles (64 b), z = 20 chunks. 256 threads.
// Dynamic smem: sA[64][136] + sB[64][136] bf16 = 34816 bytes.
__global__ __launch_bounds__(256) void k_gemm_mma(int t, int tm) {
    bf16* sA = (bf16*)smem_raw;        // [64][136]
    bf16* sB = sA + 64*136;            // [64][136]
    int chunk = blockIdx.z, qt = blockIdx.x, mo = blockIdx.y * 64;
    const bf16 *Asrc, *W0, *W1, *W2;
    size_t astride; int wstride, k0; float* part;
    if (chunk < SPLIT_A) {
        Asrc = g_l1b + (size_t)t*BB*NN; astride = NN; k0 = chunk*128;
        W0 = g_hwh; W1 = g_hwm; W2 = g_hwl; wstride = NN;
        part = g_pA + (size_t)chunk*BB*OO;
    } else {
        Asrc = g_bufb + tm*OO; astride = (size_t)DLY*OO; k0 = (chunk - SPLIT_A)*128;
        W0 = g_iewh; W1 = g_iewm; W2 = g_iewl; wstride = OO;
        part = g_pI + (size_t)(chunk - SPLIT_A)*BB*OO;
    }
    int q0 = qt*64;
    int tid = threadIdx.x;

    // load A tile: 64 rows x 128 bf16 (16 uint4 per row)
    #pragma unroll
    for (int i = 0; i < 4; i++) {
        int idx = tid + i*256;
        int r = idx >> 4, c8 = idx & 15;
        *(uint4*)(sA + r*136 + c8*8) = *(const uint4*)(Asrc + (size_t)(mo + r)*astride + k0 + c8*8);
    }

    int w = tid >> 5, lane = tid & 31, g = lane >> 2, qi = lane & 3;
    int wm = w & 3, wn = w >> 2;     // wm: m16 tile (0..3), wn: n32 half (0..1)
    float acc[4][4];
    #pragma unroll
    for (int j = 0; j < 4; j++) { acc[j][0]=0.f; acc[j][1]=0.f; acc[j][2]=0.f; acc[j][3]=0.f; }

    const bf16* Ws[3] = {W0, W1, W2};
    for (int s = 0; s < 3; s++) {
        __syncthreads();
        #pragma unroll
        for (int i = 0; i < 4; i++) {
            int idx = tid + i*256;
            int r = idx >> 4, c8 = idx & 15;
            *(uint4*)(sB + r*136 + c8*8) = *(const uint4*)(Ws[s] + (size_t)(q0 + r)*wstride + k0 + c8*8);
        }
        __syncthreads();
        #pragma unroll
        for (int k16 = 0; k16 < 8; k16++) {
            int kb = k16*16 + qi*2;
            uint32_t a0 = *(const uint32_t*)(sA + (16*wm + g    )*136 + kb    );
            uint32_t a1 = *(const uint32_t*)(sA + (16*wm + g + 8)*136 + kb    );
            uint32_t a2 = *(const uint32_t*)(sA + (16*wm + g    )*136 + kb + 8);
            uint32_t a3 = *(const uint32_t*)(sA + (16*wm + g + 8)*136 + kb + 8);
            #pragma unroll
            for (int j = 0; j < 4; j++) {
                uint32_t b0 = *(const uint32_t*)(sB + (wn*32 + j*8 + g)*136 + kb    );
                uint32_t b1 = *(const uint32_t*)(sB + (wn*32 + j*8 + g)*136 + kb + 8);
                asm volatile(
                    "mma.sync.aligned.m16n8k16.row.col.f32.bf16.bf16.f32 "
                    "{%0,%1,%2,%3},{%4,%5,%6,%7},{%8,%9},{%0,%1,%2,%3};\n"
                    : "+f"(acc[j][0]), "+f"(acc[j][1]), "+f"(acc[j][2]), "+f"(acc[j][3])
                    : "r"(a0), "r"(a1), "r"(a2), "r"(a3), "r"(b0), "r"(b1));
            }
        }
    }
    int m0 = mo + 16*wm + g;
    #pragma unroll
    for (int j = 0; j < 4; j++) {
        int qc = q0 + wn*32 + j*8 + qi*2;
        *(float2*)(part + (size_t)m0*OO + qc)       = make_float2(acc[j][0], acc[j][1]);
        *(float2*)(part + (size_t)(m0 + 8)*OO + qc) = make_float2(acc[j][2], acc[j][3]);
    }
}

// ---------------- epilogue ----------------
__global__ __launch_bounds__(256) void k_epi(float* __restrict__ out_l2, int t, int tm) {
    int qb = blockIdx.x * 16;
    int tq = threadIdx.x & 15;
    int tb = threadIdx.x >> 4;       // 0..15
    int q  = qb + tq;
    __shared__ float sh[3][16][16];

    float r2 = 0.f, ri = 0.f, rd = 0.f;
    for (int j = 0; j < 8; j++) {
        int b  = tb + 16*j;
        int bo = b*OO + q;
        float l1v = 0.f, io = 0.f;
        #pragma unroll
        for (int s = 0; s < SPLIT_A; s++) l1v = __fadd_rn(l1v, g_pA[(size_t)s*BB*OO + bo]);
        #pragma unroll
        for (int s = 0; s < SPLIT_I; s++) io  = __fadd_rn(io,  g_pI[(size_t)s*BB*OO + bo]);
        float v = fmaf(ALPHA_F, g_v2[bo], __fadd_rn(l1v, -io));
        float s2 = (v > THRESH_F) ? 1.f : 0.f;
        g_v2[bo] = (v > THRESH_F) ? 0.f : v;
        out_l2[((size_t)b*TT + t)*OO + q] = s2;
        float t2 = fmaf(DEC_F, g_tr2[bo], __fmul_rn(CDEC_F, s2));
        g_tr2[bo] = t2;
        { bf16 h, l; split2(t2, h, l); g_tr2h[bo] = h; g_tr2l[bo] = l; }
        float inh_in = __fmul_rn(s2, g_ediag[q]);
        float vv = fmaf(ALPHA_F, g_vi[bo], inh_in);
        float si = (vv > THRESH_F) ? 1.f : 0.f;
        g_vi[bo] = (vv > THRESH_F) ? 0.f : vv;
        g_bufb[((size_t)b*DLY + tm)*OO + q] = __float2bfloat16(si);
        float ti = fmaf(DEC_F, g_tri[bo], __fmul_rn(CDEC_F, si));
        g_tri[bo] = ti;
        { bf16 h, l; split2(ti, h, l); g_trih[bo] = h; g_tril[bo] = l; }
        r2 += t2; ri += ti; rd = fmaf(ti, t2, rd);
    }
    sh[0][tb][tq] = r2; sh[1][tb][tq] = ri; sh[2][tb][tq] = rd;
    __syncthreads();
    if (tb == 0) {
        float s2 = 0.f, si = 0.f, sd = 0.f;
        for (int g = 0; g < 16; g++) { s2 += sh[0][g][tq]; si += sh[1][g][tq]; sd += sh[2][g][tq]; }
        float m2 = s2 * INVB_F, mi = si * INVB_F;
        g_mtr2[q] = m2;
        float e = g_ediag[q];
        float dw = fmaf(A_PLUS_F, __fmul_rn(sd, INVB_F),
                        -__fmul_rn(__fmul_rn(A_MINUS_F, e), mi));
        g_ediag[q] = __fadd_rn(e, dw);
    }
}

// ---------------- MMA plasticity with ldmatrix.trans (no scalar transposes) ----------------
// grid: x = 40 p-tiles (0..31 hw, 32..39 iew), y = 8 q-tiles of 64. 256 threads.
// smem: sAh[128][72] + sAl[128][72] + sB[128][72] bf16 = 55296 bytes; natural [b][.] layout.
__global__ __launch_bounds__(256) void k_plast_mma(int t) {
    bf16* sAh = (bf16*)smem_raw;        // [b=128][72]  (tr2 hi, cols q)
    bf16* sAl = sAh + 128*72;
    bf16* sB  = sAl + 128*72;           // [b=128][72]  (pre, cols p)
    int bx = blockIdx.x;
    int mode = (bx >= 32);
    int p0 = (mode ? (bx - 32) : bx) * 64;
    int q0 = blockIdx.y * 64;
    const bf16* preh = mode ? g_trih : (g_tr1h + (size_t)t*BB*NN);
    const bf16* prel = mode ? g_tril : (g_tr1l + (size_t)t*BB*NN);
    int P = mode ? OO : NN;
    float* W = mode ? g_iew : g_hw;
    bf16 *Wh = mode ? g_iewh : g_hwh, *Wm = mode ? g_iewm : g_hwm, *Wl = mode ? g_iewl : g_hwl;

    int tid = threadIdx.x;
    // coalesced copy of tr2 hi/lo tiles: [128 b][64 q], 8 uint4 per row
    #pragma unroll
    for (int i = 0; i < 4; i++) {
        int idx = tid + i*256;          // 1024
        int b = idx >> 3, c8 = idx & 7;
        *(uint4*)(sAh + b*72 + c8*8) = *(const uint4*)(g_tr2h + b*OO + q0 + c8*8);
        *(uint4*)(sAl + b*72 + c8*8) = *(const uint4*)(g_tr2l + b*OO + q0 + c8*8);
    }

    int w = tid >> 5, lane = tid & 31, g = lane >> 2, qi = lane & 3;
    uint32_t base = (uint32_t)__cvta_generic_to_shared(sAh);
    int r8 = lane & 7, sel = lane >> 3;

    float acc[4][4];
    #pragma unroll
    for (int mi = 0; mi < 4; mi++) { acc[mi][0]=0.f; acc[mi][1]=0.f; acc[mi][2]=0.f; acc[mi][3]=0.f; }

    const bf16* Bs[2] = {preh, prel};
    for (int s = 0; s < 2; s++) {
        __syncthreads();
        #pragma unroll
        for (int i = 0; i < 4; i++) {
            int idx = tid + i*256;
            int b = idx >> 3, c8 = idx & 7;
            *(uint4*)(sB + b*72 + c8*8) = *(const uint4*)(Bs[s] + (size_t)b*P + p0 + c8*8);
        }
        __syncthreads();
        #pragma unroll
        for (int k16 = 0; k16 < 8; k16++) {
            int kb16 = k16*16;
            // B frags via ldmatrix.x2.trans from sB[b][p]: matrix0 rows kb16+r cols p0w..; matrix1 rows kb16+8+r
            uint32_t b0, b1;
            {
                int rr = kb16 + ((sel & 1) ? 8 : 0) + r8;
                uint32_t baddr = base + (uint32_t)(2*128*72)*2u /*unused*/;
                baddr = (uint32_t)__cvta_generic_to_shared(sB) + (uint32_t)(rr*72 + w*8) * 2u;
                asm volatile("ldmatrix.sync.aligned.m8n8.x2.trans.shared.b16 {%0,%1}, [%2];"
                             : "=r"(b0), "=r"(b1) : "r"(baddr));
            }
            #pragma unroll
            for (int mi = 0; mi < 4; mi++) {
                #pragma unroll
                for (int as = 0; as < 2; as++) {
                    const bf16* A = as ? sAl : sAh;
                    int rr = kb16 + ((sel & 2) ? 8 : 0) + r8;
                    int cc = mi*16 + ((sel & 1) ? 8 : 0);
                    uint32_t aaddr = (uint32_t)__cvta_generic_to_shared(A) + (uint32_t)(rr*72 + cc) * 2u;
                    uint32_t a0, a1, a2, a3;
                    asm volatile("ldmatrix.sync.aligned.m8n8.x4.trans.shared.b16 {%0,%1,%2,%3}, [%4];"
                                 : "=r"(a0), "=r"(a1), "=r"(a2), "=r"(a3) : "r"(aaddr));
                    asm volatile(
                        "mma.sync.aligned.m16n8k16.row.col.f32.bf16.bf16.f32 "
                        "{%0,%1,%2,%3},{%4,%5,%6,%7},{%8,%9},{%0,%1,%2,%3};\n"
                        : "+f"(acc[mi][0]), "+f"(acc[mi][1]), "+f"(acc[mi][2]), "+f"(acc[mi][3])
                        : "r"(a0), "r"(a1), "r"(a2), "r"(a3), "r"(b0), "r"(b1));
                }
            }
        }
    }

    int pc = p0 + w*8 + qi*2;
    #pragma unroll
    for (int mi = 0; mi < 4; mi++) {
        #pragma unroll
        for (int half = 0; half < 2; half++) {
            int qq = q0 + mi*16 + g + half*8;
            float h0 = acc[mi][half*2 + 0], h1 = acc[mi][half*2 + 1];
            float mean = g_mtr2[qq];
            size_t wbase = (size_t)qq*P + pc;
            float2 wv = *(float2*)(W + wbase);
            float dw0 = fmaf(A_PLUS_F, __fmul_rn(h0, INVB_F),
                             -__fmul_rn(__fmul_rn(A_MINUS_F, wv.x), mean));
            float dw1 = fmaf(A_PLUS_F, __fmul_rn(h1, INVB_F),
                             -__fmul_rn(__fmul_rn(A_MINUS_F, wv.y), mean));
            float nw0 = __fadd_rn(wv.x, dw0);
            float nw1 = __fadd_rn(wv.y, dw1);
            if (mode && qq == pc)     nw0 = 0.f;
            if (mode && qq == pc + 1) nw1 = 0.f;
            *(float2*)(W + wbase) = make_float2(nw0, nw1);
            bf16 h, m, l, h2, m2, l2;
            split3(nw0, h, m, l);
            split3(nw1, h2, m2, l2);
            *(__nv_bfloat162*)(Wh + wbase) = __nv_bfloat162(h, h2);
            *(__nv_bfloat162*)(Wm + wbase) = __nv_bfloat162(m, m2);
            *(__nv_bfloat162*)(Wl + wbase) = __nv_bfloat162(l, l2);
        }
    }
}

// ---------------- launch ----------------
extern "C" void kernel_launch(void* const* d_in, const int* in_sizes, int n_in,
                              void* d_out, int out_size) {
    const float* x      = (const float*)d_in[0];
    const float* win    = (const float*)d_in[1];
    const float* hw_in  = (const float*)d_in[2];
    const float* eiw_in = (const float*)d_in[3];
    const float* iew_in = (const float*)d_in[4];
    float* out_l1 = (float*)d_out;
    float* out_l2 = out_l1 + (size_t)BB*TT*NN;

    const int sm_gemm  = (64*136 + 64*136) * 2;   // 34816
    const int sm_plast = 3 * 128*72 * 2;          // 55296
    cudaFuncSetAttribute(k_gemm_mma,  cudaFuncAttributeMaxDynamicSharedMemorySize, sm_gemm);
    cudaFuncSetAttribute(k_plast_mma, cudaFuncAttributeMaxDynamicSharedMemorySize, sm_plast);

    k_init<<<(OO*NN)/256, 256>>>(hw_in, eiw_in, iew_in);
    k_csr<<<256, 256>>>(win);
    k_layer1_all<<<(BB*NN)/256, 256>>>(x, out_l1);

    for (int t = 0; t < TT; t++) {
        int tm = t % DLY;
        k_gemm_mma<<<dim3(8, 2, SPLIT_A + SPLIT_I), 256, sm_gemm>>>(t, tm);
        k_epi<<<32, 256>>>(out_l2, t, tm);
        k_plast_mma<<<dim3(40, 8), 256, sm_plast>>>(t);
    }
}

// round 8
// speedup vs baseline: 1.6136x; 1.3068x over previous
#include <cuda_runtime.h>
#include <cuda_bf16.h>
#include <cstdint>

#define BB 128
#define TT 100
#define NN 2048
#define OO 512
#define DLY 10

#define ALPHA_F   0.90483741803595957316f   // exp(-1/10)
#define DEC_F     0.95122942450071400910f   // exp(-1/20)
#define CDEC_F    0.04877057549928599090f   // 1 - exp(-1/20)
#define THRESH_F  0.02f
#define A_PLUS_F  1e-4f
#define A_MINUS_F 1e-4f
#define INVB_F    0.0078125f                // 1/128, exact

#define SPLIT_A 16          // hw K-chunks of 128 (K=2048)
#define SPLIT_I 4           // iew K-chunks of 128 (K=512)

typedef __nv_bfloat16 bf16;

// ---------------- state (static device globals; no allocation) ----------------
__device__ bf16  g_l1b [(size_t)TT*BB*NN];    // l1 spikes, bf16 (exact 0/1)
__device__ bf16  g_tr1h[(size_t)TT*BB*NN];    // tr1 hi split per step
__device__ bf16  g_tr1l[(size_t)TT*BB*NN];    // tr1 lo split per step
__device__ float g_v2 [BB*OO];
__device__ float g_vi [BB*OO];
__device__ float g_tr2[BB*OO];
__device__ float g_tri[BB*OO];
__device__ bf16  g_tr2h[BB*OO], g_tr2l[BB*OO];
__device__ bf16  g_trih[BB*OO], g_tril[BB*OO];
__device__ bf16  g_bufb[BB*DLY*OO];           // inh spike delay buffer (exact 0/1)
__device__ float g_hw [(size_t)OO*NN];
__device__ bf16  g_hwh[(size_t)OO*NN], g_hwm[(size_t)OO*NN], g_hwl[(size_t)OO*NN];
__device__ float g_iew[OO*OO];
__device__ bf16  g_iewh[OO*OO], g_iewm[OO*OO], g_iewl[OO*OO];
__device__ float g_ediag[OO];
__device__ float g_mtr2[OO];
__device__ float g_pA[SPLIT_A*BB*OO];
__device__ float g_pI[SPLIT_I*BB*OO];
__device__ int   g_nzcnt[NN];
__device__ int   g_nzcol[(size_t)NN*NN];
__device__ float g_nzval[(size_t)NN*NN];

__device__ __forceinline__ void split3(float w, bf16& h, bf16& m, bf16& l) {
    h = __float2bfloat16(w);
    float r1 = __fadd_rn(w, -__bfloat162float(h));
    m = __float2bfloat16(r1);
    float r2 = __fadd_rn(r1, -__bfloat162float(m));
    l = __float2bfloat16(r2);
}
__device__ __forceinline__ void split2(float w, bf16& h, bf16& l) {
    h = __float2bfloat16(w);
    l = __float2bfloat16(__fadd_rn(w, -__bfloat162float(h)));
}
__device__ __forceinline__ uint32_t s2u(const void* p) {
    return (uint32_t)__cvta_generic_to_shared(p);
}
__device__ __forceinline__ void cpa16(uint32_t d, const void* s) {
    asm volatile("cp.async.ca.shared.global [%0], [%1], 16;\n" :: "r"(d), "l"(s));
}
__device__ __forceinline__ void cpa_commit_wait() {
    asm volatile("cp.async.commit_group;\n");
    asm volatile("cp.async.wait_group 0;\n");
}

// ---------------- init ----------------
__global__ void k_init(const float* __restrict__ hw_in,
                       const float* __restrict__ eiw_in,
                       const float* __restrict__ iew_in) {
    int i = blockIdx.x * blockDim.x + threadIdx.x;   // grid covers OO*NN = 1M
    if (i < OO*NN) {
        float w = hw_in[i];
        g_hw[i] = w;
        split3(w, g_hwh[i], g_hwm[i], g_hwl[i]);
    }
    if (i < BB*DLY*OO) g_bufb[i] = __float2bfloat16(0.f);
    if (i < BB*OO) {
        g_v2[i]=0.f; g_vi[i]=0.f; g_tr2[i]=0.f; g_tri[i]=0.f;
        bf16 z = __float2bfloat16(0.f);
        g_tr2h[i]=z; g_tr2l[i]=z; g_trih[i]=z; g_tril[i]=z;
    }
    if (i < OO*OO) {
        int r = i / OO, c = i - r*OO;
        float w = (r == c) ? 0.f : iew_in[i];
        g_iew[i] = w;
        split3(w, g_iewh[i], g_iewm[i], g_iewl[i]);
    }
    if (i < OO) g_ediag[i] = eiw_in[i*OO + i];
}

// ---------------- CSR build of input_weight ----------------
__global__ void k_csr(const float* __restrict__ W) {
    int wid  = (blockIdx.x * blockDim.x + threadIdx.x) >> 5;
    int lane = threadIdx.x & 31;
    if (wid >= NN) return;
    int cnt = 0;
    for (int base = 0; base < NN; base += 32) {
        float w = W[wid*NN + base + lane];
        unsigned m = __ballot_sync(0xffffffffu, w != 0.f);
        if (w != 0.f) {
            int pos = cnt + __popc(m & ((1u << lane) - 1u));
            g_nzcol[(size_t)wid*NN + pos] = base + lane;
            g_nzval[(size_t)wid*NN + pos] = w;
        }
        cnt += __popc(m);
    }
    if (lane == 0) g_nzcnt[wid] = cnt;
}

// ---------------- layer 1: all T steps in one launch ----------------
__global__ __launch_bounds__(256) void k_layer1_all(const float* __restrict__ x,
                                                    float* __restrict__ out_l1) {
    int idx = blockIdx.x * 256 + threadIdx.x;      // grid == BB*NN
    int b = idx >> 11;
    int n = idx & (NN - 1);
    int cnt = g_nzcnt[n];
    const int*   cp = g_nzcol + (size_t)n*NN;
    const float* vp = g_nzval + (size_t)n*NN;
    const float* xb = x + (size_t)b*TT*NN;
    float v = 0.f, tr = 0.f;
    for (int t = 0; t < TT; t++) {
        const float* xr = xb + (size_t)t*NN;
        float acc = 0.f;
        for (int j = 0; j < cnt; j++) acc = fmaf(xr[cp[j]], vp[j], acc);
        v = fmaf(ALPHA_F, v, acc);
        float s = (v > THRESH_F) ? 1.f : 0.f;
        v = (v > THRESH_F) ? 0.f : v;
        tr = fmaf(DEC_F, tr, __fmul_rn(CDEC_F, s));
        size_t o = ((size_t)b*TT + t)*NN + n;
        out_l1[o] = s;
        size_t ot = ((size_t)t*BB + b)*NN + n;
        g_l1b[ot] = __float2bfloat16(s);
        bf16 h, l; split2(tr, h, l);
        g_tr1h[ot] = h; g_tr1l[ot] = l;
    }
}

extern __shared__ __align__(16) char smem_raw[];

// ---------------- MMA gemm: all 3 splits staged, single sync, hoisted A frags ----------------
// grid: x = 8 q-tiles (64 q), y = 2 m-tiles (64 b), z = 20 chunks. 256 threads.
// smem: sA[64][136] + sB[3][64][136] bf16 = 69632 bytes.
__global__ __launch_bounds__(256) void k_gemm_mma(int t, int tm) {
    bf16* sA = (bf16*)smem_raw;        // [64][136]
    bf16* sB = sA + 64*136;            // [3][64][136]
    int chunk = blockIdx.z, qt = blockIdx.x, mo = blockIdx.y * 64;
    const bf16 *Asrc, *W0, *W1, *W2;
    size_t astride; int wstride, k0; float* part;
    if (chunk < SPLIT_A) {
        Asrc = g_l1b + (size_t)t*BB*NN; astride = NN; k0 = chunk*128;
        W0 = g_hwh; W1 = g_hwm; W2 = g_hwl; wstride = NN;
        part = g_pA + (size_t)chunk*BB*OO;
    } else {
        Asrc = g_bufb + tm*OO; astride = (size_t)DLY*OO; k0 = (chunk - SPLIT_A)*128;
        W0 = g_iewh; W1 = g_iewm; W2 = g_iewl; wstride = OO;
        part = g_pI + (size_t)(chunk - SPLIT_A)*BB*OO;
    }
    int q0 = qt*64;
    int tid = threadIdx.x;
    uint32_t sAu = s2u(sA), sBu = s2u(sB);

    // async loads: A tile (64x128) + 3 B split tiles (64x128 each)
    const bf16* Ws[3] = {W0, W1, W2};
    #pragma unroll
    for (int i = 0; i < 4; i++) {
        int idx = tid + i*256;
        int r = idx >> 4, c8 = idx & 15;
        cpa16(sAu + (uint32_t)(r*136 + c8*8)*2u, Asrc + (size_t)(mo + r)*astride + k0 + c8*8);
    }
    #pragma unroll
    for (int s = 0; s < 3; s++) {
        #pragma unroll
        for (int i = 0; i < 4; i++) {
            int idx = tid + i*256;
            int r = idx >> 4, c8 = idx & 15;
            cpa16(sBu + (uint32_t)((s*64 + r)*136 + c8*8)*2u,
                  Ws[s] + (size_t)(q0 + r)*wstride + k0 + c8*8);
        }
    }
    cpa_commit_wait();
    __syncthreads();

    int w = tid >> 5, lane = tid & 31, g = lane >> 2, qi = lane & 3;
    int wm = w & 3, wn = w >> 2;
    int lr = lane & 7, lsel = lane >> 3;

    // hoist A fragments for all 8 k16 (reused across 3 splits)
    uint32_t a[8][4];
    int arow = 16*wm + lr + ((lsel & 1) ? 8 : 0);
    #pragma unroll
    for (int k16 = 0; k16 < 8; k16++) {
        int acol = k16*16 + ((lsel & 2) ? 8 : 0);
        uint32_t addr = sAu + (uint32_t)(arow*136 + acol)*2u;
        asm volatile("ldmatrix.sync.aligned.m8n8.x4.shared.b16 {%0,%1,%2,%3}, [%4];"
                     : "=r"(a[k16][0]), "=r"(a[k16][1]), "=r"(a[k16][2]), "=r"(a[k16][3])
                     : "r"(addr));
    }

    float acc[4][4];
    #pragma unroll
    for (int j = 0; j < 4; j++) { acc[j][0]=0.f; acc[j][1]=0.f; acc[j][2]=0.f; acc[j][3]=0.f; }

    int brow_base = wn*32 + lr;
    int bcol_off = (lane & 8) ? 8 : 0;
    #pragma unroll
    for (int s = 0; s < 3; s++) {
        #pragma unroll
        for (int k16 = 0; k16 < 8; k16++) {
            #pragma unroll
            for (int j = 0; j < 4; j++) {
                uint32_t b0, b1;
                uint32_t baddr = sBu + (uint32_t)((s*64 + brow_base + j*8)*136 + k16*16 + bcol_off)*2u;
                asm volatile("ldmatrix.sync.aligned.m8n8.x2.shared.b16 {%0,%1}, [%2];"
                             : "=r"(b0), "=r"(b1) : "r"(baddr));
                asm volatile(
                    "mma.sync.aligned.m16n8k16.row.col.f32.bf16.bf16.f32 "
                    "{%0,%1,%2,%3},{%4,%5,%6,%7},{%8,%9},{%0,%1,%2,%3};\n"
                    : "+f"(acc[j][0]), "+f"(acc[j][1]), "+f"(acc[j][2]), "+f"(acc[j][3])
                    : "r"(a[k16][0]), "r"(a[k16][1]), "r"(a[k16][2]), "r"(a[k16][3]),
                      "r"(b0), "r"(b1));
            }
        }
    }
    int m0 = mo + 16*wm + g;
    #pragma unroll
    for (int j = 0; j < 4; j++) {
        int qc = q0 + wn*32 + j*8 + qi*2;
        *(float2*)(part + (size_t)m0*OO + qc)       = make_float2(acc[j][0], acc[j][1]);
        *(float2*)(part + (size_t)(m0 + 8)*OO + qc) = make_float2(acc[j][2], acc[j][3]);
    }
}

// ---------------- epilogue: grid 64 blocks, 8q x 32b threads ----------------
__global__ __launch_bounds__(256) void k_epi(float* __restrict__ out_l2, int t, int tm) {
    int qb = blockIdx.x * 8;
    int tq = threadIdx.x & 7;
    int tb = threadIdx.x >> 3;       // 0..31
    int q  = qb + tq;
    __shared__ float sh[3][32][8];

    float r2 = 0.f, ri = 0.f, rd = 0.f;
    for (int j = 0; j < 4; j++) {
        int b  = tb + 32*j;
        int bo = b*OO + q;
        float l1v = 0.f, io = 0.f;
        #pragma unroll
        for (int s = 0; s < SPLIT_A; s++) l1v = __fadd_rn(l1v, g_pA[(size_t)s*BB*OO + bo]);
        #pragma unroll
        for (int s = 0; s < SPLIT_I; s++) io  = __fadd_rn(io,  g_pI[(size_t)s*BB*OO + bo]);
        float v = fmaf(ALPHA_F, g_v2[bo], __fadd_rn(l1v, -io));
        float s2 = (v > THRESH_F) ? 1.f : 0.f;
        g_v2[bo] = (v > THRESH_F) ? 0.f : v;
        out_l2[((size_t)b*TT + t)*OO + q] = s2;
        float t2 = fmaf(DEC_F, g_tr2[bo], __fmul_rn(CDEC_F, s2));
        g_tr2[bo] = t2;
        { bf16 h, l; split2(t2, h, l); g_tr2h[bo] = h; g_tr2l[bo] = l; }
        float inh_in = __fmul_rn(s2, g_ediag[q]);
        float vv = fmaf(ALPHA_F, g_vi[bo], inh_in);
        float si = (vv > THRESH_F) ? 1.f : 0.f;
        g_vi[bo] = (vv > THRESH_F) ? 0.f : vv;
        g_bufb[((size_t)b*DLY + tm)*OO + q] = __float2bfloat16(si);
        float ti = fmaf(DEC_F, g_tri[bo], __fmul_rn(CDEC_F, si));
        g_tri[bo] = ti;
        { bf16 h, l; split2(ti, h, l); g_trih[bo] = h; g_tril[bo] = l; }
        r2 += t2; ri += ti; rd = fmaf(ti, t2, rd);
    }
    sh[0][tb][tq] = r2; sh[1][tb][tq] = ri; sh[2][tb][tq] = rd;
    __syncthreads();
    if (tb == 0) {
        float s2 = 0.f, si = 0.f, sd = 0.f;
        for (int g = 0; g < 32; g++) { s2 += sh[0][g][tq]; si += sh[1][g][tq]; sd += sh[2][g][tq]; }
        float m2 = s2 * INVB_F, mi = si * INVB_F;
        g_mtr2[q] = m2;
        float e = g_ediag[q];
        float dw = fmaf(A_PLUS_F, __fmul_rn(sd, INVB_F),
                        -__fmul_rn(__fmul_rn(A_MINUS_F, e), mi));
        g_ediag[q] = __fadd_rn(e, dw);
    }
}

// ---------------- MMA plasticity: fused splits, single sync, A frag reuse ----------------
// grid: x = 40 p-tiles (0..31 hw, 32..39 iew), y = 8 q-tiles of 64. 256 threads.
// smem: sAh,sAl,sB0,sB1 each [128][72] bf16 = 73728 bytes.
__global__ __launch_bounds__(256) void k_plast_mma(int t) {
    bf16* sAh = (bf16*)smem_raw;        // [b=128][72]  (tr2 hi, cols q)
    bf16* sAl = sAh + 128*72;
    bf16* sB0 = sAl + 128*72;           // [b=128][72]  (pre hi, cols p)
    bf16* sB1 = sB0 + 128*72;
    int bx = blockIdx.x;
    int mode = (bx >= 32);
    int p0 = (mode ? (bx - 32) : bx) * 64;
    int q0 = blockIdx.y * 64;
    const bf16* preh = mode ? g_trih : (g_tr1h + (size_t)t*BB*NN);
    const bf16* prel = mode ? g_tril : (g_tr1l + (size_t)t*BB*NN);
    int P = mode ? OO : NN;
    float* W = mode ? g_iew : g_hw;
    bf16 *Wh = mode ? g_iewh : g_hwh, *Wm = mode ? g_iewm : g_hwm, *Wl = mode ? g_iewl : g_hwl;

    int tid = threadIdx.x;
    uint32_t sAhu = s2u(sAh), sAlu = s2u(sAl), sB0u = s2u(sB0), sB1u = s2u(sB1);

    #pragma unroll
    for (int i = 0; i < 4; i++) {
        int idx = tid + i*256;          // 1024
        int b = idx >> 3, c8 = idx & 7;
        uint32_t so = (uint32_t)(b*72 + c8*8)*2u;
        cpa16(sAhu + so, g_tr2h + b*OO + q0 + c8*8);
        cpa16(sAlu + so, g_tr2l + b*OO + q0 + c8*8);
        cpa16(sB0u + so, preh + (size_t)b*P + p0 + c8*8);
        cpa16(sB1u + so, prel + (size_t)b*P + p0 + c8*8);
    }
    cpa_commit_wait();
    __syncthreads();

    int w = tid >> 5, lane = tid & 31, g = lane >> 2, qi = lane & 3;
    int r8 = lane & 7, sel = lane >> 3;

    float acc[4][4];
    #pragma unroll
    for (int mi = 0; mi < 4; mi++) { acc[mi][0]=0.f; acc[mi][1]=0.f; acc[mi][2]=0.f; acc[mi][3]=0.f; }

    #pragma unroll
    for (int k16 = 0; k16 < 8; k16++) {
        int kb16 = k16*16;
        int rrB = kb16 + ((sel & 1) ? 8 : 0) + r8;
        uint32_t bo = (uint32_t)(rrB*72 + w*8)*2u;
        uint32_t bh0, bh1, bl0, bl1;
        asm volatile("ldmatrix.sync.aligned.m8n8.x2.trans.shared.b16 {%0,%1}, [%2];"
                     : "=r"(bh0), "=r"(bh1) : "r"(sB0u + bo));
        asm volatile("ldmatrix.sync.aligned.m8n8.x2.trans.shared.b16 {%0,%1}, [%2];"
                     : "=r"(bl0), "=r"(bl1) : "r"(sB1u + bo));
        int rrA = kb16 + ((sel & 2) ? 8 : 0) + r8;
        #pragma unroll
        for (int mi = 0; mi < 4; mi++) {
            int cc = mi*16 + ((sel & 1) ? 8 : 0);
            uint32_t ao = (uint32_t)(rrA*72 + cc)*2u;
            #pragma unroll
            for (int as = 0; as < 2; as++) {
                uint32_t a0, a1, a2, a3;
                asm volatile("ldmatrix.sync.aligned.m8n8.x4.trans.shared.b16 {%0,%1,%2,%3}, [%4];"
                             : "=r"(a0), "=r"(a1), "=r"(a2), "=r"(a3)
                             : "r"((as ? sAlu : sAhu) + ao));
                asm volatile(
                    "mma.sync.aligned.m16n8k16.row.col.f32.bf16.bf16.f32 "
                    "{%0,%1,%2,%3},{%4,%5,%6,%7},{%8,%9},{%0,%1,%2,%3};\n"
                    : "+f"(acc[mi][0]), "+f"(acc[mi][1]), "+f"(acc[mi][2]), "+f"(acc[mi][3])
                    : "r"(a0), "r"(a1), "r"(a2), "r"(a3), "r"(bh0), "r"(bh1));
                asm volatile(
                    "mma.sync.aligned.m16n8k16.row.col.f32.bf16.bf16.f32 "
                    "{%0,%1,%2,%3},{%4,%5,%6,%7},{%8,%9},{%0,%1,%2,%3};\n"
                    : "+f"(acc[mi][0]), "+f"(acc[mi][1]), "+f"(acc[mi][2]), "+f"(acc[mi][3])
                    : "r"(a0), "r"(a1), "r"(a2), "r"(a3), "r"(bl0), "r"(bl1));
            }
        }
    }

    int pc = p0 + w*8 + qi*2;
    #pragma unroll
    for (int mi = 0; mi < 4; mi++) {
        #pragma unroll
        for (int half = 0; half < 2; half++) {
            int qq = q0 + mi*16 + g + half*8;
            float h0 = acc[mi][half*2 + 0], h1 = acc[mi][half*2 + 1];
            float mean = g_mtr2[qq];
            size_t wbase = (size_t)qq*P + pc;
            float2 wv = *(float2*)(W + wbase);
            float dw0 = fmaf(A_PLUS_F, __fmul_rn(h0, INVB_F),
                             -__fmul_rn(__fmul_rn(A_MINUS_F, wv.x), mean));
            float dw1 = fmaf(A_PLUS_F, __fmul_rn(h1, INVB_F),
                             -__fmul_rn(__fmul_rn(A_MINUS_F, wv.y), mean));
            float nw0 = __fadd_rn(wv.x, dw0);
            float nw1 = __fadd_rn(wv.y, dw1);
            if (mode && qq == pc)     nw0 = 0.f;
            if (mode && qq == pc + 1) nw1 = 0.f;
            *(float2*)(W + wbase) = make_float2(nw0, nw1);
            bf16 h, m, l, h2, m2, l2;
            split3(nw0, h, m, l);
            split3(nw1, h2, m2, l2);
            *(__nv_bfloat162*)(Wh + wbase) = __nv_bfloat162(h, h2);
            *(__nv_bfloat162*)(Wm + wbase) = __nv_bfloat162(m, m2);
            *(__nv_bfloat162*)(Wl + wbase) = __nv_bfloat162(l, l2);
        }
    }
}

// ---------------- launch ----------------
extern "C" void kernel_launch(void* const* d_in, const int* in_sizes, int n_in,
                              void* d_out, int out_size) {
    const float* x      = (const float*)d_in[0];
    const float* win    = (const float*)d_in[1];
    const float* hw_in  = (const float*)d_in[2];
    const float* eiw_in = (const float*)d_in[3];
    const float* iew_in = (const float*)d_in[4];
    float* out_l1 = (float*)d_out;
    float* out_l2 = out_l1 + (size_t)BB*TT*NN;

    const int sm_gemm  = 4 * 64*136 * 2;   // 69632
    const int sm_plast = 4 * 128*72 * 2;   // 73728
    cudaFuncSetAttribute(k_gemm_mma,  cudaFuncAttributeMaxDynamicSharedMemorySize, sm_gemm);
    cudaFuncSetAttribute(k_plast_mma, cudaFuncAttributeMaxDynamicSharedMemorySize, sm_plast);

    k_init<<<(OO*NN)/256, 256>>>(hw_in, eiw_in, iew_in);
    k_csr<<<256, 256>>>(win);
    k_layer1_all<<<(BB*NN)/256, 256>>>(x, out_l1);

    for (int t = 0; t < TT; t++) {
        int tm = t % DLY;
        k_gemm_mma<<<dim3(8, 2, SPLIT_A + SPLIT_I), 256, sm_gemm>>>(t, tm);
        k_epi<<<64, 256>>>(out_l2, t, tm);
        k_plast_mma<<<dim3(40, 8), 256, sm_plast>>>(t);
    }
}